// round 15
// baseline (speedup 1.0000x reference)
#include <cuda_runtime.h>
#include <cuda_fp16.h>
#include <cstdint>

// ---------------- problem constants ----------------
#define M_DIM 8192
#define K_DIM 4096
#define N_DIM 16384

#define BM 128
#define BN 128
#define BKC 64                       // K elems per pipeline chunk
#define NCHUNK (K_DIM / BKC)         // 64
#define STAGES 6

#define A_TILE_B 16384               // 128 rows x 128B (64 fp16)
#define W_TILE_B 16384               // 128 rows x 128B
#define STAGE_B (A_TILE_B + W_TILE_B)        // 32768

#define SMEM_TILE0 1024
#define SMEM_TOTAL (SMEM_TILE0 + STAGES * STAGE_B)   // 197632

#define MT_M (M_DIM / BM)            // 64
#define MT_N (N_DIM / BN)            // 128
#define NTILES (MT_M * MT_N)         // 8192
#define THREADS 288                  // 8 compute warps + 1 producer warp

// ---------------- scratch: pre-swizzled fp16 tile blocks ----------------
__device__ __half g_A[(size_t)M_DIM * K_DIM];
__device__ __half g_W[(size_t)N_DIM * K_DIM];

// ---------------- PTX helpers ----------------
__device__ __forceinline__ uint32_t smem_u32(const void* p) {
    uint32_t a;
    asm("{ .reg .u64 t; cvta.to.shared.u64 t, %1; cvt.u32.u64 %0, t; }" : "=r"(a) : "l"(p));
    return a;
}
#define MBAR_INIT(addr, cnt) \
    asm volatile("mbarrier.init.shared.b64 [%0], %1;" :: "r"(addr), "r"(cnt) : "memory")
#define MBAR_EXPECT_TX(addr, bytes) \
    asm volatile("mbarrier.arrive.expect_tx.shared.b64 _, [%0], %1;" :: "r"(addr), "r"(bytes) : "memory")
#define MBAR_ARRIVE(addr) \
    asm volatile("mbarrier.arrive.shared.b64 _, [%0];" :: "r"(addr) : "memory")
#define MBAR_WAIT(addr, ph) do {                                                  \
    uint32_t _m = (addr), _p = (ph), _d;                                          \
    asm volatile("{ .reg .pred p; mbarrier.try_wait.parity.acquire.cta.shared::cta.b64 p, [%1], %2; selp.b32 %0,1,0,p; }" \
                 : "=r"(_d) : "r"(_m), "r"(_p) : "memory");                       \
    if (!_d) {                                                                    \
        asm volatile("{ .reg .pred P1; WL%=: mbarrier.try_wait.parity.acquire.cta.shared::cta.b64 P1, [%0], %1, 0x989680; @P1 bra.uni WD%=; bra.uni WL%=; WD%=: }" \
                     :: "r"(_m), "r"(_p) : "memory");                             \
    } } while (0)

__device__ __forceinline__ void bulk_g2s(uint32_t dst, const void* src, uint32_t bytes, uint32_t mbar) {
    asm volatile("cp.async.bulk.shared::cluster.global.mbarrier::complete_tx::bytes [%0], [%1], %2, [%3];"
                 :: "r"(dst), "l"(src), "r"(bytes), "r"(mbar) : "memory");
}
__device__ __forceinline__ void ldsm4(uint32_t* r, uint32_t addr) {
    asm volatile("ldmatrix.sync.aligned.m8n8.x4.shared.b16 {%0,%1,%2,%3}, [%4];"
                 : "=r"(r[0]), "=r"(r[1]), "=r"(r[2]), "=r"(r[3]) : "r"(addr));
}
__device__ __forceinline__ void mma_f16(float* c, const uint32_t* a, uint32_t b0, uint32_t b1) {
    asm volatile(
        "mma.sync.aligned.m16n8k16.row.col.f32.f16.f16.f32 "
        "{%0,%1,%2,%3},{%4,%5,%6,%7},{%8,%9},{%0,%1,%2,%3};"
        : "+f"(c[0]), "+f"(c[1]), "+f"(c[2]), "+f"(c[3])
        : "r"(a[0]), "r"(a[1]), "r"(a[2]), "r"(a[3]), "r"(b0), "r"(b1));
}
__device__ __forceinline__ uint32_t swz128(uint32_t off) { return off ^ ((off >> 3) & 0x70); }
__device__ __forceinline__ uint32_t pack_h2(float a, float b) {
    __half2 t = __floats2half2_rn(a, b);
    return *(uint32_t*)&t;
}

// ---------------- pre-pass: A fp32 -> fp16 swizzled 128-row tile blocks ----------------
__global__ void __launch_bounds__(256) convertA(const float* __restrict__ A) {
    uint32_t u = blockIdx.x * 256u + threadIdx.x;      // M*K/8 units
    uint32_t m = u >> 9;
    uint32_t k0 = (u & 511u) << 3;
    const float4* p = (const float4*)(A + ((size_t)m << 12) + k0);
    float4 f0 = p[0], f1 = p[1];
    uint4 o;
    o.x = pack_h2(f0.x, f0.y); o.y = pack_h2(f0.z, f0.w);
    o.z = pack_h2(f1.x, f1.y); o.w = pack_h2(f1.z, f1.w);
    uint32_t off = swz128((m & 127u) * 128u + (k0 & 63u) * 2u);
    size_t blk = ((size_t)(m >> 7) * NCHUNK + (k0 >> 6)) * A_TILE_B;
    *(uint4*)((char*)g_A + blk + off) = o;
}

// ---------------- pre-pass: W int32 -> fp16 swizzled 128-row tile blocks ----------------
__global__ void __launch_bounds__(256) convertW(const int* __restrict__ W) {
    uint32_t u = blockIdx.x * 256u + threadIdx.x;      // N*K/8 units
    uint32_t n = u >> 9;
    uint32_t k0 = (u & 511u) << 3;
    const int4* p = (const int4*)(W + ((size_t)n << 12) + k0);
    int4 w0 = p[0], w1 = p[1];
    uint4 o;
    o.x = pack_h2((float)w0.x, (float)w0.y);
    o.y = pack_h2((float)w0.z, (float)w0.w);
    o.z = pack_h2((float)w1.x, (float)w1.y);
    o.w = pack_h2((float)w1.z, (float)w1.w);
    uint32_t off = swz128((n & 127u) * 128u + (k0 & 63u) * 2u);
    size_t blk = ((size_t)(n >> 7) * NCHUNK + (k0 >> 6)) * W_TILE_B;
    *(uint4*)((char*)g_W + blk + off) = o;
}

// ---------------- main GEMM: persistent CTAs; per-tile R13 ring; epilogue
// hoisted past the next tile's re-init so it overlaps the producer's refill ----
__global__ void __launch_bounds__(THREADS, 1)
gemm_mma(const float* __restrict__ wscale, const float* __restrict__ bias,
         float* __restrict__ Out) {
    extern __shared__ char smem[];
    const uint32_t sb = smem_u32(smem);
    const int tid = threadIdx.x, warp = tid >> 5, lane = tid & 31;

    // ---- per-warp constants ----
    const int warp_m = warp & 3;
    const int warp_n = warp >> 2;
    const int wm0 = warp_m * 32;
    const int wn0 = warp_n * 64;

    const int rA = lane & 15;                       // A row within 16
    const int cA = (lane >> 4) * 8;                 // A col 0/8
    const int rB = (lane & 7) | ((lane & 16) >> 1); // B row within 16
    const int cB = ((lane >> 3) & 1) * 8;           // B col 0/8

    uint32_t rowOffA[2], rowOffB[4];
#pragma unroll
    for (int t = 0; t < 2; t++) rowOffA[t] = (wm0 + t * 16 + rA) * 128;
#pragma unroll
    for (int q = 0; q < 4; q++) rowOffB[q] = (wn0 + q * 16 + rB) * 128;
    const uint32_t swzA = (rA & 7) << 4;
    const uint32_t swzB = (rB & 7) << 4;
    uint32_t colA[4], colB[4];
#pragma unroll
    for (int ks = 0; ks < 4; ks++) {
        colA[ks] = (((uint32_t)(ks * 16 + cA)) * 2u) ^ swzA;
        colB[ks] = (((uint32_t)(ks * 16 + cB)) * 2u) ^ swzB;
    }
    const int groupID = lane >> 2, tig = lane & 3;

    // carried accumulators + previous-tile coords (epilogue is deferred one phase)
    float acc[2][8][4];
    int pm0 = -1, pn0 = -1;

    for (int tile = blockIdx.x; tile < NTILES; tile += gridDim.x) {
        const int l  = tile & 1023;               // 8 m-tiles x 128 n-tiles
        const int gq = tile >> 10;
        const int mt = gq * 8 + (l & 7);
        const int nt = l >> 3;
        const int m0 = mt * BM, n0 = nt * BN;

        // ---- quiesce previous tile's ring, then fresh barriers ----
        __syncthreads();
        if (tid == 0) {
#pragma unroll
            for (int s = 0; s < STAGES; s++) {
                MBAR_INIT(sb + 16 * s, 1);        // full[s] (tx-based)
                MBAR_INIT(sb + 16 * s + 8, 8);    // empty[s] (8 compute warps, lane0)
            }
        }
        __syncthreads();

        if (warp == 8) {
            // ---------------- producer warp: starts refilling immediately ----------------
            const char* bA = (const char*)g_A + (size_t)mt * NCHUNK * A_TILE_B;
            const char* bW = (const char*)g_W + (size_t)nt * NCHUNK * W_TILE_B;
            int s = 0, ph = 1;
            for (int c = 0; c < NCHUNK; c++) {
                MBAR_WAIT(sb + 16 * s + 8, (uint32_t)ph);
                if (lane == 0) {
                    uint32_t full = sb + 16 * s;
                    uint32_t td = sb + SMEM_TILE0 + s * STAGE_B;
                    MBAR_EXPECT_TX(full, (uint32_t)STAGE_B);
                    bulk_g2s(td,            bA + (size_t)c * A_TILE_B, A_TILE_B, full);
                    bulk_g2s(td + A_TILE_B, bW + (size_t)c * W_TILE_B, W_TILE_B, full);
                }
                if (++s == STAGES) { s = 0; ph ^= 1; }
            }
        } else {
            // ---------------- deferred epilogue of PREVIOUS tile ----------------
            // (overlaps the producer's refill; touches only registers + global mem)
            if (pm0 >= 0) {
#pragma unroll
                for (int t = 0; t < 2; t++) {
                    const int gm0 = pm0 + wm0 + t * 16 + groupID;
#pragma unroll
                    for (int n8 = 0; n8 < 8; n8++) {
                        const int gn = pn0 + wn0 + n8 * 8 + tig * 2;
                        const float s0 = wscale[gn], s1 = wscale[gn + 1];
                        const float b0 = bias[gn],   b1 = bias[gn + 1];
                        float2 o1, o2;
                        o1.x = fmaf(acc[t][n8][0], s0, b0);
                        o1.y = fmaf(acc[t][n8][1], s1, b1);
                        o2.x = fmaf(acc[t][n8][2], s0, b0);
                        o2.y = fmaf(acc[t][n8][3], s1, b1);
                        *(float2*)(Out + (size_t)gm0 * N_DIM + gn)       = o1;
                        *(float2*)(Out + (size_t)(gm0 + 8) * N_DIM + gn) = o2;
                    }
                }
            }

            // ---------------- compute this tile ----------------
#pragma unroll
            for (int t = 0; t < 2; t++)
#pragma unroll
                for (int n8 = 0; n8 < 8; n8++)
#pragma unroll
                    for (int i = 0; i < 4; i++) acc[t][n8][i] = 0.0f;

            int s = 0, ph = 0;
            for (int c = 0; c < NCHUNK; c++) {
                MBAR_WAIT(sb + 16 * s, (uint32_t)ph);
                const uint32_t sA = sb + SMEM_TILE0 + s * STAGE_B;
                const uint32_t sW = sA + A_TILE_B;

                // software-pipelined fragments: load ks+1 while computing ks
                uint32_t af[2][2][4], bf[2][4][4];
#pragma unroll
                for (int t = 0; t < 2; t++) ldsm4(af[0][t], sA + rowOffA[t] + colA[0]);
#pragma unroll
                for (int q = 0; q < 4; q++) ldsm4(bf[0][q], sW + rowOffB[q] + colB[0]);

#pragma unroll
                for (int ks = 0; ks < 4; ks++) {
                    const int cur = ks & 1, nxt = cur ^ 1;
                    if (ks < 3) {
#pragma unroll
                        for (int t = 0; t < 2; t++) ldsm4(af[nxt][t], sA + rowOffA[t] + colA[ks + 1]);
#pragma unroll
                        for (int q = 0; q < 4; q++) ldsm4(bf[nxt][q], sW + rowOffB[q] + colB[ks + 1]);
                    }
#pragma unroll
                    for (int t = 0; t < 2; t++)
#pragma unroll
                        for (int n8 = 0; n8 < 8; n8++) {
                            const uint32_t* b = bf[cur][n8 >> 1];
                            if (n8 & 1) mma_f16(acc[t][n8], af[cur][t], b[2], b[3]);
                            else        mma_f16(acc[t][n8], af[cur][t], b[0], b[1]);
                        }
                }
                if (lane == 0) MBAR_ARRIVE(sb + 16 * s + 8);
                if (++s == STAGES) { s = 0; ph ^= 1; }
            }

            pm0 = m0; pn0 = n0;   // epilogue deferred to next iteration (or tail)
        }
    }

    // ---------------- tail epilogue for the last tile ----------------
    if (warp != 8 && pm0 >= 0) {
#pragma unroll
        for (int t = 0; t < 2; t++) {
            const int gm0 = pm0 + wm0 + t * 16 + groupID;
#pragma unroll
            for (int n8 = 0; n8 < 8; n8++) {
                const int gn = pn0 + wn0 + n8 * 8 + tig * 2;
                const float s0 = wscale[gn], s1 = wscale[gn + 1];
                const float b0 = bias[gn],   b1 = bias[gn + 1];
                float2 o1, o2;
                o1.x = fmaf(acc[t][n8][0], s0, b0);
                o1.y = fmaf(acc[t][n8][1], s1, b1);
                o2.x = fmaf(acc[t][n8][2], s0, b0);
                o2.y = fmaf(acc[t][n8][3], s1, b1);
                *(float2*)(Out + (size_t)gm0 * N_DIM + gn)       = o1;
                *(float2*)(Out + (size_t)(gm0 + 8) * N_DIM + gn) = o2;
            }
        }
    }
}

// ---------------- launch ----------------
extern "C" void kernel_launch(void* const* d_in, const int* in_sizes, int n_in,
                              void* d_out, int out_size) {
    const float* input  = (const float*)d_in[0];   // [B,S,K] fp32
    const int*   weight = (const int*)d_in[1];     // [N,K] int32
    const float* wscale = (const float*)d_in[2];   // [N]
    const float* bias   = (const float*)d_in[3];   // [N]
    float* out = (float*)d_out;

    int nsm = 148;
    {
        int dev = 0, v = 0;
        if (cudaGetDevice(&dev) == cudaSuccess &&
            cudaDeviceGetAttribute(&v, cudaDevAttrMultiProcessorCount, dev) == cudaSuccess && v > 0)
            nsm = v;
    }

    convertA<<<(M_DIM * K_DIM / 8) / 256, 256>>>(input);   // 16384 blocks
    convertW<<<(N_DIM * K_DIM / 8) / 256, 256>>>(weight);  // 32768 blocks

    cudaFuncSetAttribute(gemm_mma, cudaFuncAttributeMaxDynamicSharedMemorySize, SMEM_TOTAL);
    gemm_mma<<<nsm, THREADS, SMEM_TOTAL>>>(wscale, bias, out);
}

// round 16
// speedup vs baseline: 1.0113x; 1.0113x over previous
#include <cuda_runtime.h>
#include <cuda_fp16.h>
#include <cstdint>

// ---------------- problem constants ----------------
#define M_DIM 8192
#define K_DIM 4096
#define N_DIM 16384

#define BM 128
#define BN 128
#define BKC 64                       // K elems per pipeline chunk
#define NCHUNK (K_DIM / BKC)         // 64
#define STAGES 6

#define A_TILE_B 16384               // 128 rows x 128B (64 fp16)
#define W_TILE_B 16384               // 128 rows x 128B
#define STAGE_B (A_TILE_B + W_TILE_B)        // 32768

#define SMEM_TILE0 1024
#define SMEM_TOTAL (SMEM_TILE0 + STAGES * STAGE_B)   // 197632

#define MT_M (M_DIM / BM)            // 64
#define MT_N (N_DIM / BN)            // 128
#define NTILES (MT_M * MT_N)         // 8192
#define THREADS 288                  // 8 compute warps + 1 producer warp

// merged convert kernel geometry: each thread handles 2 x 8-element units
#define A_UNITS (M_DIM * K_DIM / 8)          // 4194304
#define W_UNITS (N_DIM * K_DIM / 8)          // 8388608
#define CVT_THREADS 256
#define A_BLOCKS (A_UNITS / (2 * CVT_THREADS))   // 8192
#define W_BLOCKS (W_UNITS / (2 * CVT_THREADS))   // 16384
#define CVT_BLOCKS (A_BLOCKS + W_BLOCKS)         // 24576

// ---------------- scratch: pre-swizzled fp16 tile blocks ----------------
__device__ __half g_A[(size_t)M_DIM * K_DIM];
__device__ __half g_W[(size_t)N_DIM * K_DIM];

// ---------------- PTX helpers ----------------
__device__ __forceinline__ uint32_t smem_u32(const void* p) {
    uint32_t a;
    asm("{ .reg .u64 t; cvta.to.shared.u64 t, %1; cvt.u32.u64 %0, t; }" : "=r"(a) : "l"(p));
    return a;
}
#define MBAR_INIT(addr, cnt) \
    asm volatile("mbarrier.init.shared.b64 [%0], %1;" :: "r"(addr), "r"(cnt) : "memory")
#define MBAR_EXPECT_TX(addr, bytes) \
    asm volatile("mbarrier.arrive.expect_tx.shared.b64 _, [%0], %1;" :: "r"(addr), "r"(bytes) : "memory")
#define MBAR_ARRIVE(addr) \
    asm volatile("mbarrier.arrive.shared.b64 _, [%0];" :: "r"(addr) : "memory")
#define MBAR_WAIT(addr, ph) do {                                                  \
    uint32_t _m = (addr), _p = (ph), _d;                                          \
    asm volatile("{ .reg .pred p; mbarrier.try_wait.parity.acquire.cta.shared::cta.b64 p, [%1], %2; selp.b32 %0,1,0,p; }" \
                 : "=r"(_d) : "r"(_m), "r"(_p) : "memory");                       \
    if (!_d) {                                                                    \
        asm volatile("{ .reg .pred P1; WL%=: mbarrier.try_wait.parity.acquire.cta.shared::cta.b64 P1, [%0], %1, 0x989680; @P1 bra.uni WD%=; bra.uni WL%=; WD%=: }" \
                     :: "r"(_m), "r"(_p) : "memory");                             \
    } } while (0)

__device__ __forceinline__ void bulk_g2s(uint32_t dst, const void* src, uint32_t bytes, uint32_t mbar) {
    asm volatile("cp.async.bulk.shared::cluster.global.mbarrier::complete_tx::bytes [%0], [%1], %2, [%3];"
                 :: "r"(dst), "l"(src), "r"(bytes), "r"(mbar) : "memory");
}
__device__ __forceinline__ void ldsm4(uint32_t* r, uint32_t addr) {
    asm volatile("ldmatrix.sync.aligned.m8n8.x4.shared.b16 {%0,%1,%2,%3}, [%4];"
                 : "=r"(r[0]), "=r"(r[1]), "=r"(r[2]), "=r"(r[3]) : "r"(addr));
}
__device__ __forceinline__ void mma_f16(float* c, const uint32_t* a, uint32_t b0, uint32_t b1) {
    asm volatile(
        "mma.sync.aligned.m16n8k16.row.col.f32.f16.f16.f32 "
        "{%0,%1,%2,%3},{%4,%5,%6,%7},{%8,%9},{%0,%1,%2,%3};"
        : "+f"(c[0]), "+f"(c[1]), "+f"(c[2]), "+f"(c[3])
        : "r"(a[0]), "r"(a[1]), "r"(a[2]), "r"(a[3]), "r"(b0), "r"(b1));
}
__device__ __forceinline__ uint32_t swz128(uint32_t off) { return off ^ ((off >> 3) & 0x70); }
__device__ __forceinline__ uint32_t pack_h2(float a, float b) {
    __half2 t = __floats2half2_rn(a, b);
    return *(uint32_t*)&t;
}

// ---------------- merged pre-pass: A fp32->fp16 and W int32->fp16, swizzled blocks ----------------
// Blocks [0, A_BLOCKS) handle A (2 units/thread); blocks [A_BLOCKS, CVT_BLOCKS) handle W.
__global__ void __launch_bounds__(CVT_THREADS) convertAW(const float* __restrict__ A,
                                                         const int* __restrict__ W) {
    const uint32_t bid = blockIdx.x;
    if (bid < A_BLOCKS) {
#pragma unroll
        for (int h = 0; h < 2; h++) {
            uint32_t u = bid * (2u * CVT_THREADS) + h * CVT_THREADS + threadIdx.x;
            uint32_t m = u >> 9;
            uint32_t k0 = (u & 511u) << 3;
            const float4* p = (const float4*)(A + ((size_t)m << 12) + k0);
            float4 f0 = p[0], f1 = p[1];
            uint4 o;
            o.x = pack_h2(f0.x, f0.y); o.y = pack_h2(f0.z, f0.w);
            o.z = pack_h2(f1.x, f1.y); o.w = pack_h2(f1.z, f1.w);
            uint32_t off = swz128((m & 127u) * 128u + (k0 & 63u) * 2u);
            size_t blk = ((size_t)(m >> 7) * NCHUNK + (k0 >> 6)) * A_TILE_B;
            *(uint4*)((char*)g_A + blk + off) = o;
        }
    } else {
        const uint32_t wb = bid - A_BLOCKS;
#pragma unroll
        for (int h = 0; h < 2; h++) {
            uint32_t u = wb * (2u * CVT_THREADS) + h * CVT_THREADS + threadIdx.x;
            uint32_t n = u >> 9;
            uint32_t k0 = (u & 511u) << 3;
            const int4* p = (const int4*)(W + ((size_t)n << 12) + k0);
            int4 w0 = p[0], w1 = p[1];
            uint4 o;
            o.x = pack_h2((float)w0.x, (float)w0.y);
            o.y = pack_h2((float)w0.z, (float)w0.w);
            o.z = pack_h2((float)w1.x, (float)w1.y);
            o.w = pack_h2((float)w1.z, (float)w1.w);
            uint32_t off = swz128((n & 127u) * 128u + (k0 & 63u) * 2u);
            size_t blk = ((size_t)(n >> 7) * NCHUNK + (k0 >> 6)) * W_TILE_B;
            *(uint4*)((char*)g_W + blk + off) = o;
        }
    }
}

// ---------------- main GEMM: persistent CTAs; per-tile R6-identical pipeline (R13) ----------------
__global__ void __launch_bounds__(THREADS, 1)
gemm_mma(const float* __restrict__ wscale, const float* __restrict__ bias,
         float* __restrict__ Out) {
    extern __shared__ char smem[];
    const uint32_t sb = smem_u32(smem);
    const int tid = threadIdx.x, warp = tid >> 5, lane = tid & 31;

    // ---- per-warp constants ----
    const int warp_m = warp & 3;
    const int warp_n = warp >> 2;
    const int wm0 = warp_m * 32;
    const int wn0 = warp_n * 64;

    const int rA = lane & 15;                       // A row within 16
    const int cA = (lane >> 4) * 8;                 // A col 0/8
    const int rB = (lane & 7) | ((lane & 16) >> 1); // B row within 16
    const int cB = ((lane >> 3) & 1) * 8;           // B col 0/8

    uint32_t rowOffA[2], rowOffB[4];
#pragma unroll
    for (int t = 0; t < 2; t++) rowOffA[t] = (wm0 + t * 16 + rA) * 128;
#pragma unroll
    for (int q = 0; q < 4; q++) rowOffB[q] = (wn0 + q * 16 + rB) * 128;
    const uint32_t swzA = (rA & 7) << 4;
    const uint32_t swzB = (rB & 7) << 4;
    uint32_t colA[4], colB[4];
#pragma unroll
    for (int ks = 0; ks < 4; ks++) {
        colA[ks] = (((uint32_t)(ks * 16 + cA)) * 2u) ^ swzA;
        colB[ks] = (((uint32_t)(ks * 16 + cB)) * 2u) ^ swzB;
    }
    const int groupID = lane >> 2, tig = lane & 3;

    for (int tile = blockIdx.x; tile < NTILES; tile += gridDim.x) {
        const int l  = tile & 1023;               // 8 m-tiles x 128 n-tiles
        const int gq = tile >> 10;
        const int mt = gq * 8 + (l & 7);
        const int nt = l >> 3;
        const int m0 = mt * BM, n0 = nt * BN;

        // ---- fresh barrier ring each tile (ring fully quiescent at this point) ----
        if (tid == 0) {
#pragma unroll
            for (int s = 0; s < STAGES; s++) {
                MBAR_INIT(sb + 16 * s, 1);        // full[s] (tx-based)
                MBAR_INIT(sb + 16 * s + 8, 8);    // empty[s] (8 compute warps, lane0)
            }
        }
        __syncthreads();

        if (warp == 8) {
            // ---------------- producer warp (per tile) ----------------
            const char* bA = (const char*)g_A + (size_t)mt * NCHUNK * A_TILE_B;
            const char* bW = (const char*)g_W + (size_t)nt * NCHUNK * W_TILE_B;
            int s = 0, ph = 1;
            for (int c = 0; c < NCHUNK; c++) {
                MBAR_WAIT(sb + 16 * s + 8, (uint32_t)ph);
                if (lane == 0) {
                    uint32_t full = sb + 16 * s;
                    uint32_t td = sb + SMEM_TILE0 + s * STAGE_B;
                    MBAR_EXPECT_TX(full, (uint32_t)STAGE_B);
                    bulk_g2s(td,            bA + (size_t)c * A_TILE_B, A_TILE_B, full);
                    bulk_g2s(td + A_TILE_B, bW + (size_t)c * W_TILE_B, W_TILE_B, full);
                }
                if (++s == STAGES) { s = 0; ph ^= 1; }
            }
        } else {
            // ---------------- compute warps 0..7 (per tile) ----------------
            float acc[2][8][4];
#pragma unroll
            for (int t = 0; t < 2; t++)
#pragma unroll
                for (int n8 = 0; n8 < 8; n8++)
#pragma unroll
                    for (int i = 0; i < 4; i++) acc[t][n8][i] = 0.0f;

            int s = 0, ph = 0;
            for (int c = 0; c < NCHUNK; c++) {
                MBAR_WAIT(sb + 16 * s, (uint32_t)ph);
                const uint32_t sA = sb + SMEM_TILE0 + s * STAGE_B;
                const uint32_t sW = sA + A_TILE_B;

                // software-pipelined fragments: load ks+1 while computing ks
                uint32_t af[2][2][4], bf[2][4][4];
#pragma unroll
                for (int t = 0; t < 2; t++) ldsm4(af[0][t], sA + rowOffA[t] + colA[0]);
#pragma unroll
                for (int q = 0; q < 4; q++) ldsm4(bf[0][q], sW + rowOffB[q] + colB[0]);

#pragma unroll
                for (int ks = 0; ks < 4; ks++) {
                    const int cur = ks & 1, nxt = cur ^ 1;
                    if (ks < 3) {
#pragma unroll
                        for (int t = 0; t < 2; t++) ldsm4(af[nxt][t], sA + rowOffA[t] + colA[ks + 1]);
#pragma unroll
                        for (int q = 0; q < 4; q++) ldsm4(bf[nxt][q], sW + rowOffB[q] + colB[ks + 1]);
                    }
#pragma unroll
                    for (int t = 0; t < 2; t++)
#pragma unroll
                        for (int n8 = 0; n8 < 8; n8++) {
                            const uint32_t* b = bf[cur][n8 >> 1];
                            if (n8 & 1) mma_f16(acc[t][n8], af[cur][t], b[2], b[3]);
                            else        mma_f16(acc[t][n8], af[cur][t], b[0], b[1]);
                        }
                }
                if (lane == 0) MBAR_ARRIVE(sb + 16 * s + 8);
                if (++s == STAGES) { s = 0; ph ^= 1; }
            }

            // ---------------- epilogue: out = acc * scale[n] + bias[n] ----------------
#pragma unroll
            for (int t = 0; t < 2; t++) {
                const int gm0 = m0 + wm0 + t * 16 + groupID;
#pragma unroll
                for (int n8 = 0; n8 < 8; n8++) {
                    const int gn = n0 + wn0 + n8 * 8 + tig * 2;
                    const float s0 = wscale[gn], s1 = wscale[gn + 1];
                    const float b0 = bias[gn],   b1 = bias[gn + 1];
                    float2 o1, o2;
                    o1.x = fmaf(acc[t][n8][0], s0, b0);
                    o1.y = fmaf(acc[t][n8][1], s1, b1);
                    o2.x = fmaf(acc[t][n8][2], s0, b0);
                    o2.y = fmaf(acc[t][n8][3], s1, b1);
                    *(float2*)(Out + (size_t)gm0 * N_DIM + gn)       = o1;
                    *(float2*)(Out + (size_t)(gm0 + 8) * N_DIM + gn) = o2;
                }
            }
        }

        // ---- quiesce: all fills consumed, all arrives retired -> safe to re-init ----
        __syncthreads();
    }
}

// ---------------- launch ----------------
extern "C" void kernel_launch(void* const* d_in, const int* in_sizes, int n_in,
                              void* d_out, int out_size) {
    const float* input  = (const float*)d_in[0];   // [B,S,K] fp32
    const int*   weight = (const int*)d_in[1];     // [N,K] int32
    const float* wscale = (const float*)d_in[2];   // [N]
    const float* bias   = (const float*)d_in[3];   // [N]
    float* out = (float*)d_out;

    int nsm = 148;
    {
        int dev = 0, v = 0;
        if (cudaGetDevice(&dev) == cudaSuccess &&
            cudaDeviceGetAttribute(&v, cudaDevAttrMultiProcessorCount, dev) == cudaSuccess && v > 0)
            nsm = v;
    }

    convertAW<<<CVT_BLOCKS, CVT_THREADS>>>(input, weight);   // 24576 blocks, one ramp/drain

    cudaFuncSetAttribute(gemm_mma, cudaFuncAttributeMaxDynamicSharedMemorySize, SMEM_TOTAL);
    gemm_mma<<<nsm, THREADS, SMEM_TOTAL>>>(wscale, bias, out);
}